// round 2
// baseline (speedup 1.0000x reference)
#include <cuda_runtime.h>
#include <math.h>

// ---------------- problem constants ----------------
#define B_SZ   2
#define SEQL   2048
#define DM     2048
#define DI     4096
#define DS     128
#define HD     64
#define NH     64
#define CH     256
#define NC     8
#define CONV_DIM 4352           // DI + 2*DS
#define DPROJ    8512           // 2*DI + 2*DS + NH
#define EPSV   1e-5f
#define BL     (B_SZ * SEQL)    // 4096 rows

// ---------------- device scratch (static, no cudaMalloc) ----------------
__device__ float g_zxbcdt[(size_t)BL * DPROJ];     // in_proj output      (139.5 MB)
__device__ float g_conv  [(size_t)BL * CONV_DIM];  // conv+silu output    (71.3 MB)
__device__ float g_dt    [BL * NH];                // softplus(dt)
__device__ float g_acs   [B_SZ * NH * NC * CH];    // per-chunk cumsum(dA)
__device__ float g_states[B_SZ * NC * NH * HD * DS];
__device__ float g_prev  [B_SZ * NC * NH * HD * DS];
__device__ float g_y     [(size_t)BL * DI];        // Y then normalized y

// ---------------- generic SGEMM: C[M,N] = A[M,K] * Bw[N,K]^T ----------------
// 128x128 tile, K-step 8, 256 threads, 8x8 microtile (split-column mapping).
__global__ void __launch_bounds__(256) sgemm_tn(const float* __restrict__ A,
                                                const float* __restrict__ Bw,
                                                float* __restrict__ C,
                                                int M, int N, int K)
{
    __shared__ float As[8][128];
    __shared__ float Bs[8][128];
    const int tid = threadIdx.x;
    const int tx  = tid & 15;
    const int ty  = tid >> 4;
    const int mBase = blockIdx.y * 128;
    const int nBase = blockIdx.x * 128;
    const int lr = tid >> 1;
    const int lc = (tid & 1) * 4;

    float acc[8][8];
#pragma unroll
    for (int i = 0; i < 8; i++)
#pragma unroll
        for (int j = 0; j < 8; j++) acc[i][j] = 0.f;

    for (int k0 = 0; k0 < K; k0 += 8) {
        float4 av = make_float4(0.f, 0.f, 0.f, 0.f);
        float4 bv = make_float4(0.f, 0.f, 0.f, 0.f);
        int gm = mBase + lr;
        if (gm < M) av = *reinterpret_cast<const float4*>(&A[(size_t)gm * K + k0 + lc]);
        int gn = nBase + lr;
        if (gn < N) bv = *reinterpret_cast<const float4*>(&Bw[(size_t)gn * K + k0 + lc]);
        __syncthreads();
        As[lc + 0][lr] = av.x; As[lc + 1][lr] = av.y;
        As[lc + 2][lr] = av.z; As[lc + 3][lr] = av.w;
        Bs[lc + 0][lr] = bv.x; Bs[lc + 1][lr] = bv.y;
        Bs[lc + 2][lr] = bv.z; Bs[lc + 3][lr] = bv.w;
        __syncthreads();
#pragma unroll
        for (int kk = 0; kk < 8; kk++) {
            float a[8], b[8];
#pragma unroll
            for (int i = 0; i < 4; i++) {
                a[i]     = As[kk][ty * 4 + i];
                a[4 + i] = As[kk][64 + ty * 4 + i];
                b[i]     = Bs[kk][tx * 4 + i];
                b[4 + i] = Bs[kk][64 + tx * 4 + i];
            }
#pragma unroll
            for (int i = 0; i < 8; i++)
#pragma unroll
                for (int j = 0; j < 8; j++)
                    acc[i][j] = fmaf(a[i], b[j], acc[i][j]);
        }
    }
#pragma unroll
    for (int i = 0; i < 8; i++) {
        int r = mBase + ((i < 4) ? (ty * 4 + i) : (64 + ty * 4 + i - 4));
        if (r >= M) continue;
#pragma unroll
        for (int j = 0; j < 8; j++) {
            int cc = nBase + ((j < 4) ? (tx * 4 + j) : (64 + tx * 4 + j - 4));
            if (cc < N) C[(size_t)r * N + cc] = acc[i][j];
        }
    }
}

// ---------------- depthwise causal conv (width 4) + bias + silu ----------------
__global__ void conv_silu_kernel(const float* __restrict__ conv_w,
                                 const float* __restrict__ conv_b)
{
    int idx = blockIdx.x * blockDim.x + threadIdx.x;
    if (idx >= BL * CONV_DIM) return;
    int ch = idx % CONV_DIM;
    int l  = (idx / CONV_DIM) % SEQL;
    int b  = idx / (CONV_DIM * SEQL);
    float acc = conv_b[ch];
#pragma unroll
    for (int j = 0; j < 4; j++) {
        int t = l - 3 + j;
        if (t >= 0)
            acc = fmaf(conv_w[ch * 4 + j],
                       g_zxbcdt[(size_t)(b * SEQL + t) * DPROJ + DI + ch], acc);
    }
    g_conv[(size_t)(b * SEQL + l) * CONV_DIM + ch] = acc / (1.f + expf(-acc));
}

// ---------------- dt = softplus(raw + dt_bias) ----------------
__global__ void dt_kernel(const float* __restrict__ dt_bias)
{
    int idx = blockIdx.x * blockDim.x + threadIdx.x;
    if (idx >= BL * NH) return;
    int hh  = idx % NH;
    int row = idx / NH;
    float v = g_zxbcdt[(size_t)row * DPROJ + DI + CONV_DIM + hh] + dt_bias[hh];
    g_dt[idx] = (v > 20.f) ? v : log1pf(expf(v));
}

// ---------------- per-chunk inclusive cumsum of dA = dt * A ----------------
// block = one (b, h, c), 256 threads = chunk length
__global__ void scan_kernel(const float* __restrict__ A_log)
{
    const int bc = blockIdx.x;          // ((b*NH + h)*NC + c)
    const int c  = bc % NC;
    const int h  = (bc / NC) % NH;
    const int b  = bc / (NC * NH);
    const int l  = threadIdx.x;
    const float A = -expf(A_log[h]);
    float v = g_dt[(size_t)(b * SEQL + c * CH + l) * NH + h] * A;
    __shared__ float s[CH];
    s[l] = v;
    __syncthreads();
    for (int off = 1; off < CH; off <<= 1) {
        float t = (l >= off) ? s[l - off] : 0.f;
        __syncthreads();
        s[l] += t;
        __syncthreads();
    }
    g_acs[(size_t)bc * CH + l] = s[l];
}

// ---------------- per-chunk states: states[h,p,n] = sum_l X*dt*decay * B ----------------
// block = one (b, c, h). output 64p x 128n, 256 threads, 4x8 microtile.
__global__ void __launch_bounds__(256) states_kernel()
{
    __shared__ float Bs[32][129];
    __shared__ float Xs[32][65];
    const int tid = threadIdx.x;
    const int tx  = tid & 15;
    const int ty  = tid >> 4;
    const int h = blockIdx.x % NH;
    const int c = (blockIdx.x / NH) % NC;
    const int b = blockIdx.x / (NH * NC);
    const size_t rowBase = (size_t)(b * SEQL + c * CH);
    const size_t acsBase = ((size_t)(b * NH + h) * NC + c) * CH;
    const float acsLast = g_acs[acsBase + CH - 1];

    float acc[4][8];
#pragma unroll
    for (int i = 0; i < 4; i++)
#pragma unroll
        for (int j = 0; j < 8; j++) acc[i][j] = 0.f;

    for (int s0 = 0; s0 < CH; s0 += 32) {
        __syncthreads();
#pragma unroll
        for (int it = 0; it < 4; it++) {
            int slot = tid + it * 256;
            int sr = slot >> 5;
            int n4 = (slot & 31) * 4;
            float4 v = *reinterpret_cast<const float4*>(
                &g_conv[(rowBase + s0 + sr) * CONV_DIM + DI + n4]);
            Bs[sr][n4 + 0] = v.x; Bs[sr][n4 + 1] = v.y;
            Bs[sr][n4 + 2] = v.z; Bs[sr][n4 + 3] = v.w;
        }
#pragma unroll
        for (int it = 0; it < 2; it++) {
            int slot = tid + it * 256;
            int sr = slot >> 4;
            int p4 = (slot & 15) * 4;
            size_t row = rowBase + s0 + sr;
            float sc = g_dt[row * NH + h] * expf(acsLast - g_acs[acsBase + s0 + sr]);
            float4 v = *reinterpret_cast<const float4*>(&g_conv[row * CONV_DIM + h * HD + p4]);
            Xs[sr][p4 + 0] = v.x * sc; Xs[sr][p4 + 1] = v.y * sc;
            Xs[sr][p4 + 2] = v.z * sc; Xs[sr][p4 + 3] = v.w * sc;
        }
        __syncthreads();
#pragma unroll 8
        for (int s = 0; s < 32; s++) {
            float a[4], bb[8];
#pragma unroll
            for (int i = 0; i < 4; i++) a[i] = Xs[s][ty * 4 + i];
#pragma unroll
            for (int j = 0; j < 4; j++) {
                bb[j]     = Bs[s][tx * 4 + j];
                bb[4 + j] = Bs[s][64 + tx * 4 + j];
            }
#pragma unroll
            for (int i = 0; i < 4; i++)
#pragma unroll
                for (int j = 0; j < 8; j++)
                    acc[i][j] = fmaf(a[i], bb[j], acc[i][j]);
        }
    }
    const size_t base = ((size_t)(b * NC + c) * NH + h) * (HD * DS);
#pragma unroll
    for (int i = 0; i < 4; i++) {
        int p = ty * 4 + i;
#pragma unroll
        for (int j = 0; j < 8; j++) {
            int n = (j < 4) ? (tx * 4 + j) : (64 + tx * 4 + j - 4);
            g_states[base + (size_t)p * DS + n] = acc[i][j];
        }
    }
}

// ---------------- inter-chunk recurrence: prev[c] = exp(csum_{c-1})*prev[c-1] + states[c-1]
__global__ void chunk_rec_kernel()
{
    int idx = blockIdx.x * blockDim.x + threadIdx.x;
    if (idx >= B_SZ * NH * HD * DS) return;
    int n = idx % DS;
    int p = (idx / DS) % HD;
    int h = (idx / (DS * HD)) % NH;
    int b = idx / (DS * HD * NH);
    float prev = 0.f;
#pragma unroll
    for (int c = 0; c < NC; c++) {
        size_t off = (((size_t)(b * NC + c) * NH + h) * HD + p) * DS + n;
        g_prev[off] = prev;
        float cs = g_acs[((size_t)(b * NH + h) * NC + c) * CH + CH - 1];
        prev = expf(cs) * prev + g_states[off];
    }
}

// ---------------- SSD core: Y = (C B^T o L) X + exp(acs) * C prev^T + D*x ----------------
// block = (b, c, h, lt) with lt selecting 128-row half of the 256-chunk.
struct YS {
    float Cn [DS][129];   // C transposed  [n][l]
    float Bn [DS][33];    // B transposed  [n][s]
    float Pt [32][129];   // masked scores [s][l]
    float Xd [32][65];    // X*dt          [s][p]
    float Pvn[DS][65];    // prev transposed [n][p]
    float acsl[128];
    float acss[32];
};
extern __shared__ char y_smem_raw[];

__global__ void __launch_bounds__(256) y_kernel(const float* __restrict__ Dvec)
{
    YS& S = *reinterpret_cast<YS*>(y_smem_raw);
    const int tid = threadIdx.x;
    const int h  = blockIdx.x % NH;
    const int c  = (blockIdx.x / NH) % NC;
    const int b  = blockIdx.x / (NH * NC);
    const int lt = blockIdx.y;
    const size_t rowBase = (size_t)(b * SEQL + c * CH);
    const size_t acsBase = ((size_t)(b * NH + h) * NC + c) * CH;
    const int ly = tid >> 3;   // 0..31 -> 4 l-rows each
    const int px = tid & 7;    // 0..7  -> cols

    // C tile (128 l x 128 n), transposed into smem
#pragma unroll
    for (int it = 0; it < 16; it++) {
        int slot = tid + it * 256;
        int l  = slot >> 5;
        int n4 = (slot & 31) * 4;
        float4 v = *reinterpret_cast<const float4*>(
            &g_conv[(rowBase + lt * 128 + l) * CONV_DIM + DI + DS + n4]);
        S.Cn[n4 + 0][l] = v.x; S.Cn[n4 + 1][l] = v.y;
        S.Cn[n4 + 2][l] = v.z; S.Cn[n4 + 3][l] = v.w;
    }
    if (tid < 128) S.acsl[tid] = g_acs[acsBase + lt * 128 + tid];
    // prev state (64p x 128n), transposed
    const size_t pvBase = ((size_t)(b * NC + c) * NH + h) * (HD * DS);
#pragma unroll
    for (int it = 0; it < 8; it++) {
        int slot = tid + it * 256;
        int p  = slot >> 5;
        int n4 = (slot & 31) * 4;
        float4 v = *reinterpret_cast<const float4*>(&g_prev[pvBase + (size_t)p * DS + n4]);
        S.Pvn[n4 + 0][p] = v.x; S.Pvn[n4 + 1][p] = v.y;
        S.Pvn[n4 + 2][p] = v.z; S.Pvn[n4 + 3][p] = v.w;
    }

    float yacc[4][8];
#pragma unroll
    for (int i = 0; i < 4; i++)
#pragma unroll
        for (int j = 0; j < 8; j++) yacc[i][j] = 0.f;

    const int nst = 4 * (lt + 1);   // causal: only s-tiles with s0 <= lt*128+96
    for (int st = 0; st < nst; st++) {
        const int s0 = st * 32;
        __syncthreads();
        // B tile (32 s x 128 n), transposed
#pragma unroll
        for (int it = 0; it < 4; it++) {
            int slot = tid + it * 256;
            int sr = slot >> 5;
            int n4 = (slot & 31) * 4;
            float4 v = *reinterpret_cast<const float4*>(
                &g_conv[(rowBase + s0 + sr) * CONV_DIM + DI + n4]);
            S.Bn[n4 + 0][sr] = v.x; S.Bn[n4 + 1][sr] = v.y;
            S.Bn[n4 + 2][sr] = v.z; S.Bn[n4 + 3][sr] = v.w;
        }
        // X*dt tile (32 s x 64 p)
#pragma unroll
        for (int it = 0; it < 2; it++) {
            int slot = tid + it * 256;
            int sr = slot >> 4;
            int p4 = (slot & 15) * 4;
            size_t row = rowBase + s0 + sr;
            float dt = g_dt[row * NH + h];
            float4 v = *reinterpret_cast<const float4*>(&g_conv[row * CONV_DIM + h * HD + p4]);
            S.Xd[sr][p4 + 0] = v.x * dt; S.Xd[sr][p4 + 1] = v.y * dt;
            S.Xd[sr][p4 + 2] = v.z * dt; S.Xd[sr][p4 + 3] = v.w * dt;
        }
        if (tid < 32) S.acss[tid] = g_acs[acsBase + s0 + tid];
        __syncthreads();

        // Phase A: S[l,s] = sum_n C[l,n] B[s,n]   (4l x 4s per thread)
        float sa[4][4];
#pragma unroll
        for (int i = 0; i < 4; i++)
#pragma unroll
            for (int j = 0; j < 4; j++) sa[i][j] = 0.f;
#pragma unroll 4
        for (int n = 0; n < DS; n++) {
            float a[4], bb[4];
#pragma unroll
            for (int i = 0; i < 4; i++) a[i]  = S.Cn[n][ly * 4 + i];
#pragma unroll
            for (int j = 0; j < 4; j++) bb[j] = S.Bn[n][px * 4 + j];
#pragma unroll
            for (int i = 0; i < 4; i++)
#pragma unroll
                for (int j = 0; j < 4; j++)
                    sa[i][j] = fmaf(a[i], bb[j], sa[i][j]);
        }
        // mask + decay, store transposed for phase B
#pragma unroll
        for (int i = 0; i < 4; i++) {
            int l  = ly * 4 + i;
            int lg = lt * 128 + l;
            float al = S.acsl[l];
#pragma unroll
            for (int j = 0; j < 4; j++) {
                int sl = px * 4 + j;
                int sg = s0 + sl;
                float w = (sg <= lg) ? expf(al - S.acss[sl]) * sa[i][j] : 0.f;
                S.Pt[sl][l] = w;
            }
        }
        __syncthreads();
        // Phase B: Y[l,p] += sum_s P[l,s] Xd[s,p]   (4l x 8p per thread)
#pragma unroll 8
        for (int s = 0; s < 32; s++) {
            float a[4], bb[8];
#pragma unroll
            for (int i = 0; i < 4; i++) a[i] = S.Pt[s][ly * 4 + i];
#pragma unroll
            for (int j = 0; j < 4; j++) {
                bb[j]     = S.Xd[s][px * 4 + j];
                bb[4 + j] = S.Xd[s][32 + px * 4 + j];
            }
#pragma unroll
            for (int i = 0; i < 4; i++)
#pragma unroll
                for (int j = 0; j < 8; j++)
                    yacc[i][j] = fmaf(a[i], bb[j], yacc[i][j]);
        }
    }

    // Y_off: O[l,p] = sum_n C[l,n] prev[p,n]
    float oacc[4][8];
#pragma unroll
    for (int i = 0; i < 4; i++)
#pragma unroll
        for (int j = 0; j < 8; j++) oacc[i][j] = 0.f;
#pragma unroll 4
    for (int n = 0; n < DS; n++) {
        float a[4], bb[8];
#pragma unroll
        for (int i = 0; i < 4; i++) a[i] = S.Cn[n][ly * 4 + i];
#pragma unroll
        for (int j = 0; j < 4; j++) {
            bb[j]     = S.Pvn[n][px * 4 + j];
            bb[4 + j] = S.Pvn[n][32 + px * 4 + j];
        }
#pragma unroll
        for (int i = 0; i < 4; i++)
#pragma unroll
            for (int j = 0; j < 8; j++)
                oacc[i][j] = fmaf(a[i], bb[j], oacc[i][j]);
    }

    const float Dh = Dvec[h];
#pragma unroll
    for (int i = 0; i < 4; i++) {
        int l = ly * 4 + i;
        size_t row = rowBase + lt * 128 + l;
        float el = expf(S.acsl[l]);
#pragma unroll
        for (int j = 0; j < 8; j++) {
            int p = (j < 4) ? (px * 4 + j) : (32 + px * 4 + j - 4);
            float xs = g_conv[row * CONV_DIM + h * HD + p];
            g_y[row * DI + h * HD + p] = yacc[i][j] + el * oacc[i][j] + Dh * xs;
        }
    }
}

// ---------------- gate with silu(z) + RMSNorm (in place on g_y) ----------------
__global__ void __launch_bounds__(256) gate_norm_kernel(const float* __restrict__ norm_w)
{
    const int row = blockIdx.x;
    const float* yrow = &g_y[(size_t)row * DI];
    const float* zrow = &g_zxbcdt[(size_t)row * DPROJ];   // z = first DI entries
    float vals[16];
    float ss = 0.f;
#pragma unroll
    for (int it = 0; it < 16; it++) {
        int i = threadIdx.x + it * 256;
        float z  = zrow[i];
        float yg = yrow[i] * (z / (1.f + expf(-z)));
        vals[it] = yg;
        ss = fmaf(yg, yg, ss);
    }
    __shared__ float red[8];
#pragma unroll
    for (int o = 16; o > 0; o >>= 1) ss += __shfl_xor_sync(0xffffffffu, ss, o);
    if ((threadIdx.x & 31) == 0) red[threadIdx.x >> 5] = ss;
    __syncthreads();
    float tot = 0.f;
#pragma unroll
    for (int w = 0; w < 8; w++) tot += red[w];
    float scale = rsqrtf(tot / (float)DI + EPSV);
    float* yw = &g_y[(size_t)row * DI];
#pragma unroll
    for (int it = 0; it < 16; it++) {
        int i = threadIdx.x + it * 256;
        yw[i] = vals[it] * scale * norm_w[i];
    }
}

// ---------------- launch ----------------
extern "C" void kernel_launch(void* const* d_in, const int* in_sizes, int n_in,
                              void* d_out, int out_size)
{
    (void)in_sizes; (void)n_in; (void)out_size;
    const float* x        = (const float*)d_in[0];
    const float* in_proj  = (const float*)d_in[1];
    const float* conv_w   = (const float*)d_in[2];
    const float* conv_b   = (const float*)d_in[3];
    const float* dt_bias  = (const float*)d_in[4];
    const float* A_log    = (const float*)d_in[5];
    const float* Dv       = (const float*)d_in[6];
    const float* norm_w   = (const float*)d_in[7];
    const float* out_proj = (const float*)d_in[8];
    float* out = (float*)d_out;

    float* zx = nullptr;
    float* yb = nullptr;
    cudaGetSymbolAddress((void**)&zx, g_zxbcdt);
    cudaGetSymbolAddress((void**)&yb, g_y);

    cudaFuncSetAttribute(y_kernel, cudaFuncAttributeMaxDynamicSharedMemorySize,
                         (int)sizeof(YS));

    // 1. in_proj GEMM: [BL, DPROJ] = x[BL, DM] * W[DPROJ, DM]^T
    sgemm_tn<<<dim3((DPROJ + 127) / 128, BL / 128), 256>>>(x, in_proj, zx, BL, DPROJ, DM);
    // 2. depthwise conv + silu
    conv_silu_kernel<<<(BL * CONV_DIM + 255) / 256, 256>>>(conv_w, conv_b);
    // 3. dt = softplus
    dt_kernel<<<(BL * NH + 255) / 256, 256>>>(dt_bias);
    // 4. per-chunk cumsum of dA
    scan_kernel<<<B_SZ * NH * NC, CH>>>(A_log);
    // 5. per-chunk states
    states_kernel<<<B_SZ * NC * NH, 256>>>();
    // 6. inter-chunk recurrence
    chunk_rec_kernel<<<(B_SZ * NH * HD * DS + 255) / 256, 256>>>();
    // 7. SSD core -> Y
    y_kernel<<<dim3(B_SZ * NC * NH, 2), 256, sizeof(YS)>>>(Dv);
    // 8. gate + RMSNorm
    gate_norm_kernel<<<BL, 256>>>(norm_w);
    // 9. out_proj GEMM: out[BL, DM] = y[BL, DI] * W[DM, DI]^T
    sgemm_tn<<<dim3(DM / 128, BL / 128), 256>>>(yb, out_proj, out, BL, DM, DI);
}

// round 4
// speedup vs baseline: 1.3604x; 1.3604x over previous
#include <cuda_runtime.h>
#include <math.h>
#include <stdint.h>

// ---------------- problem constants ----------------
#define B_SZ   2
#define SEQL   2048
#define DM     2048
#define DI     4096
#define DS     128
#define HD     64
#define NH     64
#define CH     256
#define NC     8
#define CONV_DIM 4352           // DI + 2*DS
#define DPROJ    8512           // 2*DI + 2*DS + NH
#define EPSV   1e-5f
#define BL     (B_SZ * SEQL)    // 4096 rows

// ---------------- device scratch (static, no cudaMalloc) ----------------
__device__ float g_zxbcdt[(size_t)BL * DPROJ];     // in_proj output
__device__ float g_conv  [(size_t)BL * CONV_DIM];  // conv+silu output
__device__ float g_dt    [BL * NH];                // softplus(dt)
__device__ float g_acs   [B_SZ * NH * NC * CH];    // per-chunk cumsum(dA)
__device__ float g_states[B_SZ * NC * NH * HD * DS];
__device__ float g_prev  [B_SZ * NC * NH * HD * DS];
__device__ float g_y     [(size_t)BL * DI];        // Y then normalized y

// ================= TF32 tensor-core GEMM (3xTF32 split) =================
// C[M,N] = A[M,K] * Bw[N,K]^T.   fp32 in/out, fp32-level accuracy.
// Block tile 128x128, K-step 32, 256 threads (8 warps, 2x4 -> 64x32 warp tile).

__device__ __forceinline__ void mma_tf32(float c[4], const uint32_t a[4],
                                         const uint32_t b[2])
{
    asm volatile(
        "mma.sync.aligned.m16n8k8.row.col.f32.tf32.tf32.f32 "
        "{%0,%1,%2,%3}, {%4,%5,%6,%7}, {%8,%9}, {%0,%1,%2,%3};\n"
        : "+f"(c[0]), "+f"(c[1]), "+f"(c[2]), "+f"(c[3])
        : "r"(a[0]), "r"(a[1]), "r"(a[2]), "r"(a[3]),
          "r"(b[0]), "r"(b[1]));
}

// split x into tf32-representable hi (mantissa truncation) + exact residual lo
__device__ __forceinline__ void tf32_split(float x, uint32_t& hi, uint32_t& lo)
{
    uint32_t u = __float_as_uint(x) & 0xFFFFE000u;
    hi = u;
    lo = __float_as_uint(x - __uint_as_float(u));
}

#define GSTR 36   // smem row stride (floats): bank = (4*m + k) mod 32 -> conflict-free frags

__global__ void __launch_bounds__(256) gemm_tf32_tn(const float* __restrict__ A,
                                                    const float* __restrict__ Bw,
                                                    float* __restrict__ C,
                                                    int M, int N, int K)
{
    __shared__ float As[128][GSTR];
    __shared__ float Bs[128][GSTR];

    const int tid  = threadIdx.x;
    const int warp = tid >> 5;
    const int lane = tid & 31;
    const int g    = lane >> 2;      // groupID 0..7
    const int tig  = lane & 3;       // thread-in-group 0..3
    const int wm   = warp >> 2;      // 0..1  -> 64-row slab
    const int wn   = warp & 3;       // 0..3  -> 32-col slab

    const int mBase = blockIdx.y * 128;
    const int nBase = blockIdx.x * 128;

    // GLD mapping: row r = tid>>1 (coalesced 128B per row pair), k segment 16
    const int r    = tid >> 1;
    const int kseg = (tid & 1) * 16;

    float acc[4][4][4];
#pragma unroll
    for (int mt = 0; mt < 4; mt++)
#pragma unroll
        for (int nt = 0; nt < 4; nt++)
#pragma unroll
            for (int e = 0; e < 4; e++) acc[mt][nt][e] = 0.f;

    const float* aRow = A  + (size_t)(mBase + r) * K + kseg;
    const int    gn   = nBase + r;
    const float* bRow = Bw + (size_t)gn * K + kseg;
    const bool   bOk  = (gn < N);

    float4 stgA[4], stgB[4];
#pragma unroll
    for (int j = 0; j < 4; j++) {
        stgA[j] = *reinterpret_cast<const float4*>(aRow + 4 * j);
        stgB[j] = bOk ? *reinterpret_cast<const float4*>(bRow + 4 * j)
                      : make_float4(0.f, 0.f, 0.f, 0.f);
    }

    for (int k0 = 0; k0 < K; k0 += 32) {
        __syncthreads();
#pragma unroll
        for (int j = 0; j < 4; j++) {
            *reinterpret_cast<float4*>(&As[r][kseg + 4 * j]) = stgA[j];
            *reinterpret_cast<float4*>(&Bs[r][kseg + 4 * j]) = stgB[j];
        }
        __syncthreads();

        if (k0 + 32 < K) {
#pragma unroll
            for (int j = 0; j < 4; j++) {
                stgA[j] = *reinterpret_cast<const float4*>(aRow + k0 + 32 + 4 * j);
                stgB[j] = bOk ? *reinterpret_cast<const float4*>(bRow + k0 + 32 + 4 * j)
                              : make_float4(0.f, 0.f, 0.f, 0.f);
            }
        }

#pragma unroll
        for (int ks = 0; ks < 4; ks++) {
            const int kk = ks * 8;
            // B fragments for the 4 n-tiles
            uint32_t bh[4][2], bl[4][2];
#pragma unroll
            for (int nt = 0; nt < 4; nt++) {
                float b0 = Bs[wn * 32 + nt * 8 + g][kk + tig];
                float b1 = Bs[wn * 32 + nt * 8 + g][kk + tig + 4];
                tf32_split(b0, bh[nt][0], bl[nt][0]);
                tf32_split(b1, bh[nt][1], bl[nt][1]);
            }
#pragma unroll
            for (int mt = 0; mt < 4; mt++) {
                const int mrow = wm * 64 + mt * 16;
                uint32_t ah[4], al[4];
                float a0 = As[mrow + g    ][kk + tig];
                float a1 = As[mrow + g + 8][kk + tig];
                float a2 = As[mrow + g    ][kk + tig + 4];
                float a3 = As[mrow + g + 8][kk + tig + 4];
                tf32_split(a0, ah[0], al[0]);
                tf32_split(a1, ah[1], al[1]);
                tf32_split(a2, ah[2], al[2]);
                tf32_split(a3, ah[3], al[3]);
#pragma unroll
                for (int nt = 0; nt < 4; nt++) {
                    mma_tf32(acc[mt][nt], ah, bh[nt]);   // hi*hi
                    mma_tf32(acc[mt][nt], ah, bl[nt]);   // hi*lo
                    mma_tf32(acc[mt][nt], al, bh[nt]);   // lo*hi
                }
            }
        }
    }

    // epilogue
#pragma unroll
    for (int mt = 0; mt < 4; mt++) {
        const int row0 = mBase + wm * 64 + mt * 16 + g;
#pragma unroll
        for (int nt = 0; nt < 4; nt++) {
            const int col = nBase + wn * 32 + nt * 8 + 2 * tig;
            if (col < N) {
                float2 v01 = make_float2(acc[mt][nt][0], acc[mt][nt][1]);
                float2 v23 = make_float2(acc[mt][nt][2], acc[mt][nt][3]);
                *reinterpret_cast<float2*>(&C[(size_t)row0 * N + col])       = v01;
                *reinterpret_cast<float2*>(&C[(size_t)(row0 + 8) * N + col]) = v23;
            }
        }
    }
}

// ---------------- depthwise causal conv (width 4) + bias + silu ----------------
__global__ void conv_silu_kernel(const float* __restrict__ conv_w,
                                 const float* __restrict__ conv_b)
{
    int idx = blockIdx.x * blockDim.x + threadIdx.x;
    if (idx >= BL * CONV_DIM) return;
    int ch = idx % CONV_DIM;
    int l  = (idx / CONV_DIM) % SEQL;
    int b  = idx / (CONV_DIM * SEQL);
    float acc = conv_b[ch];
#pragma unroll
    for (int j = 0; j < 4; j++) {
        int t = l - 3 + j;
        if (t >= 0)
            acc = fmaf(conv_w[ch * 4 + j],
                       g_zxbcdt[(size_t)(b * SEQL + t) * DPROJ + DI + ch], acc);
    }
    g_conv[(size_t)(b * SEQL + l) * CONV_DIM + ch] = acc / (1.f + expf(-acc));
}

// ---------------- dt = softplus(raw + dt_bias) ----------------
__global__ void dt_kernel(const float* __restrict__ dt_bias)
{
    int idx = blockIdx.x * blockDim.x + threadIdx.x;
    if (idx >= BL * NH) return;
    int hh  = idx % NH;
    int row = idx / NH;
    float v = g_zxbcdt[(size_t)row * DPROJ + DI + CONV_DIM + hh] + dt_bias[hh];
    g_dt[idx] = (v > 20.f) ? v : log1pf(expf(v));
}

// ---------------- per-chunk inclusive cumsum of dA = dt * A ----------------
__global__ void scan_kernel(const float* __restrict__ A_log)
{
    const int bc = blockIdx.x;          // ((b*NH + h)*NC + c)
    const int c  = bc % NC;
    const int h  = (bc / NC) % NH;
    const int b  = bc / (NC * NH);
    const int l  = threadIdx.x;
    const float A = -expf(A_log[h]);
    float v = g_dt[(size_t)(b * SEQL + c * CH + l) * NH + h] * A;
    __shared__ float s[CH];
    s[l] = v;
    __syncthreads();
    for (int off = 1; off < CH; off <<= 1) {
        float t = (l >= off) ? s[l - off] : 0.f;
        __syncthreads();
        s[l] += t;
        __syncthreads();
    }
    g_acs[(size_t)bc * CH + l] = s[l];
}

// ---------------- per-chunk states ----------------
__global__ void __launch_bounds__(256) states_kernel()
{
    __shared__ float Bs[32][129];
    __shared__ float Xs[32][65];
    const int tid = threadIdx.x;
    const int tx  = tid & 15;
    const int ty  = tid >> 4;
    const int h = blockIdx.x % NH;
    const int c = (blockIdx.x / NH) % NC;
    const int b = blockIdx.x / (NH * NC);
    const size_t rowBase = (size_t)(b * SEQL + c * CH);
    const size_t acsBase = ((size_t)(b * NH + h) * NC + c) * CH;
    const float acsLast = g_acs[acsBase + CH - 1];

    float acc[4][8];
#pragma unroll
    for (int i = 0; i < 4; i++)
#pragma unroll
        for (int j = 0; j < 8; j++) acc[i][j] = 0.f;

    for (int s0 = 0; s0 < CH; s0 += 32) {
        __syncthreads();
#pragma unroll
        for (int it = 0; it < 4; it++) {
            int slot = tid + it * 256;
            int sr = slot >> 5;
            int n4 = (slot & 31) * 4;
            float4 v = *reinterpret_cast<const float4*>(
                &g_conv[(rowBase + s0 + sr) * CONV_DIM + DI + n4]);
            Bs[sr][n4 + 0] = v.x; Bs[sr][n4 + 1] = v.y;
            Bs[sr][n4 + 2] = v.z; Bs[sr][n4 + 3] = v.w;
        }
#pragma unroll
        for (int it = 0; it < 2; it++) {
            int slot = tid + it * 256;
            int sr = slot >> 4;
            int p4 = (slot & 15) * 4;
            size_t row = rowBase + s0 + sr;
            float sc = g_dt[row * NH + h] * expf(acsLast - g_acs[acsBase + s0 + sr]);
            float4 v = *reinterpret_cast<const float4*>(&g_conv[row * CONV_DIM + h * HD + p4]);
            Xs[sr][p4 + 0] = v.x * sc; Xs[sr][p4 + 1] = v.y * sc;
            Xs[sr][p4 + 2] = v.z * sc; Xs[sr][p4 + 3] = v.w * sc;
        }
        __syncthreads();
#pragma unroll 8
        for (int s = 0; s < 32; s++) {
            float a[4], bb[8];
#pragma unroll
            for (int i = 0; i < 4; i++) a[i] = Xs[s][ty * 4 + i];
#pragma unroll
            for (int j = 0; j < 4; j++) {
                bb[j]     = Bs[s][tx * 4 + j];
                bb[4 + j] = Bs[s][64 + tx * 4 + j];
            }
#pragma unroll
            for (int i = 0; i < 4; i++)
#pragma unroll
                for (int j = 0; j < 8; j++)
                    acc[i][j] = fmaf(a[i], bb[j], acc[i][j]);
        }
    }
    const size_t base = ((size_t)(b * NC + c) * NH + h) * (HD * DS);
#pragma unroll
    for (int i = 0; i < 4; i++) {
        int p = ty * 4 + i;
#pragma unroll
        for (int j = 0; j < 8; j++) {
            int n = (j < 4) ? (tx * 4 + j) : (64 + tx * 4 + j - 4);
            g_states[base + (size_t)p * DS + n] = acc[i][j];
        }
    }
}

// ---------------- inter-chunk recurrence ----------------
__global__ void chunk_rec_kernel()
{
    int idx = blockIdx.x * blockDim.x + threadIdx.x;
    if (idx >= B_SZ * NH * HD * DS) return;
    int n = idx % DS;
    int p = (idx / DS) % HD;
    int h = (idx / (DS * HD)) % NH;
    int b = idx / (DS * HD * NH);
    float prev = 0.f;
#pragma unroll
    for (int c = 0; c < NC; c++) {
        size_t off = (((size_t)(b * NC + c) * NH + h) * HD + p) * DS + n;
        g_prev[off] = prev;
        float cs = g_acs[((size_t)(b * NH + h) * NC + c) * CH + CH - 1];
        prev = expf(cs) * prev + g_states[off];
    }
}

// ---------------- SSD core ----------------
struct YS {
    float Cn [DS][129];
    float Bn [DS][33];
    float Pt [32][129];
    float Xd [32][65];
    float Pvn[DS][65];
    float acsl[128];
    float acss[32];
};
extern __shared__ char y_smem_raw[];

__global__ void __launch_bounds__(256) y_kernel(const float* __restrict__ Dvec)
{
    YS& S = *reinterpret_cast<YS*>(y_smem_raw);
    const int tid = threadIdx.x;
    const int h  = blockIdx.x % NH;
    const int c  = (blockIdx.x / NH) % NC;
    const int b  = blockIdx.x / (NH * NC);
    const int lt = blockIdx.y;
    const size_t rowBase = (size_t)(b * SEQL + c * CH);
    const size_t acsBase = ((size_t)(b * NH + h) * NC + c) * CH;
    const int ly = tid >> 3;
    const int px = tid & 7;

#pragma unroll
    for (int it = 0; it < 16; it++) {
        int slot = tid + it * 256;
        int l  = slot >> 5;
        int n4 = (slot & 31) * 4;
        float4 v = *reinterpret_cast<const float4*>(
            &g_conv[(rowBase + lt * 128 + l) * CONV_DIM + DI + DS + n4]);
        S.Cn[n4 + 0][l] = v.x; S.Cn[n4 + 1][l] = v.y;
        S.Cn[n4 + 2][l] = v.z; S.Cn[n4 + 3][l] = v.w;
    }
    if (tid < 128) S.acsl[tid] = g_acs[acsBase + lt * 128 + tid];
    const size_t pvBase = ((size_t)(b * NC + c) * NH + h) * (HD * DS);
#pragma unroll
    for (int it = 0; it < 8; it++) {
        int slot = tid + it * 256;
        int p  = slot >> 5;
        int n4 = (slot & 31) * 4;
        float4 v = *reinterpret_cast<const float4*>(&g_prev[pvBase + (size_t)p * DS + n4]);
        S.Pvn[n4 + 0][p] = v.x; S.Pvn[n4 + 1][p] = v.y;
        S.Pvn[n4 + 2][p] = v.z; S.Pvn[n4 + 3][p] = v.w;
    }

    float yacc[4][8];
#pragma unroll
    for (int i = 0; i < 4; i++)
#pragma unroll
        for (int j = 0; j < 8; j++) yacc[i][j] = 0.f;

    const int nst = 4 * (lt + 1);
    for (int st = 0; st < nst; st++) {
        const int s0 = st * 32;
        __syncthreads();
#pragma unroll
        for (int it = 0; it < 4; it++) {
            int slot = tid + it * 256;
            int sr = slot >> 5;
            int n4 = (slot & 31) * 4;
            float4 v = *reinterpret_cast<const float4*>(
                &g_conv[(rowBase + s0 + sr) * CONV_DIM + DI + n4]);
            S.Bn[n4 + 0][sr] = v.x; S.Bn[n4 + 1][sr] = v.y;
            S.Bn[n4 + 2][sr] = v.z; S.Bn[n4 + 3][sr] = v.w;
        }
#pragma unroll
        for (int it = 0; it < 2; it++) {
            int slot = tid + it * 256;
            int sr = slot >> 4;
            int p4 = (slot & 15) * 4;
            size_t row = rowBase + s0 + sr;
            float dt = g_dt[row * NH + h];
            float4 v = *reinterpret_cast<const float4*>(&g_conv[row * CONV_DIM + h * HD + p4]);
            S.Xd[sr][p4 + 0] = v.x * dt; S.Xd[sr][p4 + 1] = v.y * dt;
            S.Xd[sr][p4 + 2] = v.z * dt; S.Xd[sr][p4 + 3] = v.w * dt;
        }
        if (tid < 32) S.acss[tid] = g_acs[acsBase + s0 + tid];
        __syncthreads();

        float sa[4][4];
#pragma unroll
        for (int i = 0; i < 4; i++)
#pragma unroll
            for (int j = 0; j < 4; j++) sa[i][j] = 0.f;
#pragma unroll 4
        for (int n = 0; n < DS; n++) {
            float a[4], bb[4];
#pragma unroll
            for (int i = 0; i < 4; i++) a[i]  = S.Cn[n][ly * 4 + i];
#pragma unroll
            for (int j = 0; j < 4; j++) bb[j] = S.Bn[n][px * 4 + j];
#pragma unroll
            for (int i = 0; i < 4; i++)
#pragma unroll
                for (int j = 0; j < 4; j++)
                    sa[i][j] = fmaf(a[i], bb[j], sa[i][j]);
        }
#pragma unroll
        for (int i = 0; i < 4; i++) {
            int l  = ly * 4 + i;
            int lg = lt * 128 + l;
            float al = S.acsl[l];
#pragma unroll
            for (int j = 0; j < 4; j++) {
                int sl = px * 4 + j;
                int sg = s0 + sl;
                float w = (sg <= lg) ? expf(al - S.acss[sl]) * sa[i][j] : 0.f;
                S.Pt[sl][l] = w;
            }
        }
        __syncthreads();
#pragma unroll 8
        for (int s = 0; s < 32; s++) {
            float a[4], bb[8];
#pragma unroll
            for (int i = 0; i < 4; i++) a[i] = S.Pt[s][ly * 4 + i];
#pragma unroll
            for (int j = 0; j < 4; j++) {
                bb[j]     = S.Xd[s][px * 4 + j];
                bb[4 + j] = S.Xd[s][32 + px * 4 + j];
            }
#pragma unroll
            for (int i = 0; i < 4; i++)
#pragma unroll
                for (int j = 0; j < 8; j++)
                    yacc[i][j] = fmaf(a[i], bb[j], yacc[i][j]);
        }
    }

    float oacc[4][8];
#pragma unroll
    for (int i = 0; i < 4; i++)
#pragma unroll
        for (int j = 0; j < 8; j++) oacc[i][j] = 0.f;
#pragma unroll 4
    for (int n = 0; n < DS; n++) {
        float a[4], bb[8];
#pragma unroll
        for (int i = 0; i < 4; i++) a[i] = S.Cn[n][ly * 4 + i];
#pragma unroll
        for (int j = 0; j < 4; j++) {
            bb[j]     = S.Pvn[n][px * 4 + j];
            bb[4 + j] = S.Pvn[n][32 + px * 4 + j];
        }
#pragma unroll
        for (int i = 0; i < 4; i++)
#pragma unroll
            for (int j = 0; j < 8; j++)
                oacc[i][j] = fmaf(a[i], bb[j], oacc[i][j]);
    }

    const float Dh = Dvec[h];
#pragma unroll
    for (int i = 0; i < 4; i++) {
        int l = ly * 4 + i;
        size_t row = rowBase + lt * 128 + l;
        float el = expf(S.acsl[l]);
#pragma unroll
        for (int j = 0; j < 8; j++) {
            int p = (j < 4) ? (px * 4 + j) : (32 + px * 4 + j - 4);
            float xs = g_conv[row * CONV_DIM + h * HD + p];
            g_y[row * DI + h * HD + p] = yacc[i][j] + el * oacc[i][j] + Dh * xs;
        }
    }
}

// ---------------- gate with silu(z) + RMSNorm ----------------
__global__ void __launch_bounds__(256) gate_norm_kernel(const float* __restrict__ norm_w)
{
    const int row = blockIdx.x;
    const float* yrow = &g_y[(size_t)row * DI];
    const float* zrow = &g_zxbcdt[(size_t)row * DPROJ];
    float vals[16];
    float ss = 0.f;
#pragma unroll
    for (int it = 0; it < 16; it++) {
        int i = threadIdx.x + it * 256;
        float z  = zrow[i];
        float yg = yrow[i] * (z / (1.f + expf(-z)));
        vals[it] = yg;
        ss = fmaf(yg, yg, ss);
    }
    __shared__ float red[8];
#pragma unroll
    for (int o = 16; o > 0; o >>= 1) ss += __shfl_xor_sync(0xffffffffu, ss, o);
    if ((threadIdx.x & 31) == 0) red[threadIdx.x >> 5] = ss;
    __syncthreads();
    float tot = 0.f;
#pragma unroll
    for (int w = 0; w < 8; w++) tot += red[w];
    float scale = rsqrtf(tot / (float)DI + EPSV);
    float* yw = &g_y[(size_t)row * DI];
#pragma unroll
    for (int it = 0; it < 16; it++) {
        int i = threadIdx.x + it * 256;
        yw[i] = vals[it] * scale * norm_w[i];
    }
}

// ---------------- launch ----------------
extern "C" void kernel_launch(void* const* d_in, const int* in_sizes, int n_in,
                              void* d_out, int out_size)
{
    (void)in_sizes; (void)n_in; (void)out_size;
    const float* x        = (const float*)d_in[0];
    const float* in_proj  = (const float*)d_in[1];
    const float* conv_w   = (const float*)d_in[2];
    const float* conv_b   = (const float*)d_in[3];
    const float* dt_bias  = (const float*)d_in[4];
    const float* A_log    = (const float*)d_in[5];
    const float* Dv       = (const float*)d_in[6];
    const float* norm_w   = (const float*)d_in[7];
    const float* out_proj = (const float*)d_in[8];
    float* out = (float*)d_out;

    float* zx = nullptr;
    float* yb = nullptr;
    cudaGetSymbolAddress((void**)&zx, g_zxbcdt);
    cudaGetSymbolAddress((void**)&yb, g_y);

    cudaFuncSetAttribute(y_kernel, cudaFuncAttributeMaxDynamicSharedMemorySize,
                         (int)sizeof(YS));

    // 1. in_proj GEMM (tf32 tensor cores, 3xTF32): [BL, DPROJ] = x * W^T
    gemm_tf32_tn<<<dim3((DPROJ + 127) / 128, BL / 128), 256>>>(x, in_proj, zx, BL, DPROJ, DM);
    // 2. depthwise conv + silu
    conv_silu_kernel<<<(BL * CONV_DIM + 255) / 256, 256>>>(conv_w, conv_b);
    // 3. dt = softplus
    dt_kernel<<<(BL * NH + 255) / 256, 256>>>(dt_bias);
    // 4. per-chunk cumsum of dA
    scan_kernel<<<B_SZ * NH * NC, CH>>>(A_log);
    // 5. per-chunk states
    states_kernel<<<B_SZ * NC * NH, 256>>>();
    // 6. inter-chunk recurrence
    chunk_rec_kernel<<<(B_SZ * NH * HD * DS + 255) / 256, 256>>>();
    // 7. SSD core -> Y
    y_kernel<<<dim3(B_SZ * NC * NH, 2), 256, sizeof(YS)>>>(Dv);
    // 8. gate + RMSNorm
    gate_norm_kernel<<<BL, 256>>>(norm_w);
    // 9. out_proj GEMM (tf32 tensor cores, 3xTF32): out = y * W^T
    gemm_tf32_tn<<<dim3(DM / 128, BL / 128), 256>>>(yb, out_proj, out, BL, DM, DI);
}